// round 3
// baseline (speedup 1.0000x reference)
#include <cuda_runtime.h>
#include <math.h>
#include <stdint.h>

#define BATCH 32
#define MM 5120
#define NC 80
#define TOPK 1000

// ---------------- scratch (device globals: no allocation allowed) -------------
__device__ float g_scores[BATCH * MM];
__device__ int   g_labels[BATCH * MM];
__device__ float g_ssc[BATCH][TOPK];
__device__ float g_bx1[BATCH][TOPK];
__device__ float g_by1[BATCH][TOPK];
__device__ float g_bx2[BATCH][TOPK];
__device__ float g_by2[BATCH][TOPK];
__device__ float g_bar[BATCH][TOPK];
__device__ __align__(16) unsigned int g_mask[BATCH][TOPK][32];   // 4.1 MB

// ---------------- kernel 1: per-anchor score + label -------------------------
// one warp per row of 80 class logits.
// NUMERICALLY FROZEN (R1-passing version): scores feed a discrete top-k
// selection; any bit change reorders near-ties and corrupts labels output.
__global__ void k1_score(const float* __restrict__ conf,
                         const float* __restrict__ cls) {
    int gw   = (blockIdx.x * blockDim.x + threadIdx.x) >> 5;   // global row
    int lane = threadIdx.x & 31;
    if (gw >= BATCH * MM) return;
    const float* c = cls + (size_t)gw * NC;
    float e0 = c[lane];
    float e1 = c[lane + 32];
    float e2 = (lane < 16) ? c[lane + 64] : -INFINITY;

    // local argmax, first occurrence wins (strict >)
    float m = e0; int mi = lane;
    if (e1 > m) { m = e1; mi = lane + 32; }
    if (e2 > m) { m = e2; mi = lane + 64; }
    // warp reduce (tie -> smaller index, matching jnp.argmax)
    #pragma unroll
    for (int off = 16; off; off >>= 1) {
        float om = __shfl_xor_sync(0xffffffffu, m,  off);
        int   oi = __shfl_xor_sync(0xffffffffu, mi, off);
        if (om > m || (om == m && oi < mi)) { m = om; mi = oi; }
    }
    float s = expf(e0 - m) + expf(e1 - m) + ((lane < 16) ? expf(e2 - m) : 0.0f);
    #pragma unroll
    for (int off = 16; off; off >>= 1)
        s += __shfl_xor_sync(0xffffffffu, s, off);

    if (lane == 0) {
        float cf  = conf[gw];
        float sig = 1.0f / (1.0f + expf(-cf));
        g_scores[gw] = sig / s;     // sigmoid * max(softmax) = sigmoid / sumexp
        g_labels[gw] = mi;
    }
}

// ---------------- kernel 2: per-batch exact top-1000 + decode ------------------
#define OFF_HIST   0          // u32[32768]  (128KB)
#define OFF_DKEYS  131072     // u32[5120]
#define OFF_GD     151552     // u32[5120]
#define OFF_GIDX   172032     // u16[5120]
#define OFF_WS     182272     // u32[32]
#define SMEM_BYTES 182784
// top-1000 arrays (valid after selection; overlap dkeys which is dead):
#define OFF_SIDX   131072     // u32[1000]
#define OFF_SSC    135072     // f32[1000]

__global__ void __launch_bounds__(1024, 1)
k2_select(const float* __restrict__ reg_pred,
          const float* __restrict__ anchors,
          float* __restrict__ out) {
    extern __shared__ unsigned char smem[];
    unsigned int*   hist   = (unsigned int*)(smem + OFF_HIST);
    unsigned int*   dkeys  = (unsigned int*)(smem + OFF_DKEYS);
    unsigned int*   gd     = (unsigned int*)(smem + OFF_GD);
    unsigned short* gidx   = (unsigned short*)(smem + OFF_GIDX);
    unsigned int*   wsums  = (unsigned int*)(smem + OFF_WS);
    unsigned int*   sidx   = (unsigned int*)(smem + OFF_SIDX);
    float*          sscore = (float*)(smem + OFF_SSC);

    const int b    = blockIdx.x;
    const int tid  = threadIdx.x;
    const int warp = tid >> 5;
    const int lane = tid & 31;
    const float* sc = g_scores + (size_t)b * MM;

    // ---- S1: zero histogram ----
    for (int i = tid; i < 32768; i += 1024) hist[i] = 0u;
    __syncthreads();

    // ---- S2: keys + histogram. key d = ~bits(score): ascending d == descending score.
    for (int i = tid; i < MM; i += 1024) {
        unsigned int d = ~__float_as_uint(sc[i]);
        dkeys[i] = d;
        atomicAdd(&hist[d >> 17], 1u);
    }
    __syncthreads();

    // ---- S3: exclusive prefix sum over 32768 bins (32 per thread) ----
    {
        int base = tid * 32;
        unsigned int s = 0;
        #pragma unroll 8
        for (int k = 0; k < 32; k++) s += hist[base + k];
        unsigned int v = s;
        #pragma unroll
        for (int off = 1; off < 32; off <<= 1) {
            unsigned int t = __shfl_up_sync(0xffffffffu, v, off);
            if (lane >= off) v += t;
        }
        if (lane == 31) wsums[warp] = v;
        __syncthreads();
        if (tid < 32) {
            unsigned int w = wsums[tid];
            #pragma unroll
            for (int off = 1; off < 32; off <<= 1) {
                unsigned int t = __shfl_up_sync(0xffffffffu, w, off);
                if (tid >= off) w += t;
            }
            wsums[tid] = w;
        }
        __syncthreads();
        unsigned int run = (v - s) + ((warp > 0) ? wsums[warp - 1] : 0u);
        #pragma unroll 8
        for (int k = 0; k < 32; k++) {
            unsigned int h = hist[base + k];
            hist[base + k] = run;
            run += h;
        }
    }
    __syncthreads();

    // ---- S4: scatter into bin-grouped order (post: hist[b] = cum[b+1]) ----
    for (int i = tid; i < MM; i += 1024) {
        unsigned int d = dkeys[i];
        unsigned int p = atomicAdd(&hist[d >> 17], 1u);
        gd[p]   = d;
        gidx[p] = (unsigned short)i;
    }
    __syncthreads();

    // ---- S5: exact rank within bin -> top-1000 (stable: (score desc, idx asc)) ----
    for (int p = tid; p < MM; p += 1024) {
        unsigned int d   = gd[p];
        unsigned int idx = gidx[p];
        unsigned int bin = d >> 17;
        unsigned int start = hist[bin - 1];   // == orig cum[bin]
        if (start >= TOPK) continue;
        unsigned int end = hist[bin];         // == orig cum[bin+1]
        unsigned int r = start;
        for (unsigned int q = start; q < end; q++) {
            unsigned int dq = gd[q];
            if (dq < d || (dq == d && gidx[q] < idx)) r++;
        }
        if (r < TOPK) { sidx[r] = idx; sscore[r] = __uint_as_float(~d); }
    }
    __syncthreads();

    // ---- S6: decode boxes; outputs labels/bboxes; stash offset boxes to globals --
    for (int k = tid; k < TOPK; k += 1024) {
        unsigned int idx = sidx[k];
        const float* rp = reg_pred + ((size_t)b * MM + idx) * 4;
        float tx = rp[0], ty = rp[1], tw = rp[2], th = rp[3];
        const float* an = anchors + (size_t)idx * 4;
        float ax = an[0], ay = an[1], aw = an[2], ah = an[3];
        float cx = (1.0f / (1.0f + expf(-tx))) * 16.0f + ax;
        float cy = (1.0f / (1.0f + expf(-ty))) * 16.0f + ay;
        float w  = expf(tw) * aw;
        float h  = expf(th) * ah;
        float x1 = fminf(fmaxf((cx - 0.5f * w) * (1.0f / 512.0f), 0.0f), 1.0f);
        float y1 = fminf(fmaxf((cy - 0.5f * h) * (1.0f / 512.0f), 0.0f), 1.0f);
        float x2 = fminf(fmaxf((cx + 0.5f * w) * (1.0f / 512.0f), 0.0f), 1.0f);
        float y2 = fminf(fmaxf((cy + 0.5f * h) * (1.0f / 512.0f), 0.0f), 1.0f);
        float lf  = (float)g_labels[(size_t)b * MM + idx];
        float off = 2.0f * lf;
        float ox1 = x1 + off, oy1 = y1 + off, ox2 = x2 + off, oy2 = y2 + off;
        g_bx1[b][k] = ox1; g_by1[b][k] = oy1;
        g_bx2[b][k] = ox2; g_by2[b][k] = oy2;
        g_bar[b][k] = (ox2 - ox1) * (oy2 - oy1);   // areas from offset boxes (ref-exact)
        g_ssc[b][k] = sscore[k];
        // outputs: labels + bboxes
        out[32000 + b * TOPK + k] = lf;
        size_t bb = 64000 + ((size_t)b * TOPK + k) * 4;
        out[bb + 0] = x1; out[bb + 1] = y1; out[bb + 2] = x2; out[bb + 3] = y2;
    }
}

// ---------------- kernel 3: suppression mask, full-chip parallel ---------------
// row layout: g_mask[b][i][w] bit (j&31) set iff (j>i) && iou(i,j)>0.6, j=w*32+lane
#define K3_TILES  8
#define K3_ROWS   (TOPK / K3_TILES)    // 125
__global__ void __launch_bounds__(256)
k3_mask() {
    __shared__ float sx1[TOPK], sy1[TOPK], sx2[TOPK], sy2[TOPK], sar[TOPK];
    const int b    = blockIdx.x >> 3;
    const int tile = blockIdx.x & 7;
    const int tid  = threadIdx.x;
    const int warp = tid >> 5;
    const int lane = tid & 31;

    for (int t = tid; t < TOPK; t += 256) {
        sx1[t] = g_bx1[b][t]; sy1[t] = g_by1[b][t];
        sx2[t] = g_bx2[b][t]; sy2[t] = g_by2[b][t];
        sar[t] = g_bar[b][t];
    }
    __syncthreads();

    const int ibeg = tile * K3_ROWS;
    for (int i = ibeg + warp; i < ibeg + K3_ROWS; i += 8) {
        float ix1 = sx1[i], iy1 = sy1[i], ix2 = sx2[i], iy2 = sy2[i], ia = sar[i];
        int w0 = i >> 5;                 // words below w0 are all-zero (j<i only)
        #pragma unroll 4
        for (int w = w0; w < 32; w++) {
            int j = w * 32 + lane;
            bool sup = false;
            if (j > i && j < TOPK) {
                float xx1 = fmaxf(sx1[j], ix1);
                float yy1 = fmaxf(sy1[j], iy1);
                float xx2 = fminf(sx2[j], ix2);
                float yy2 = fminf(sy2[j], iy2);
                float ww = fmaxf(1e-28f, xx2 - xx1);
                float hh = fmaxf(1e-28f, yy2 - yy1);
                float inter = ww * hh;
                float iou = inter / (sar[j] + ia - inter + 1e-14f);
                sup = iou > 0.6f;
            }
            unsigned int word = __ballot_sync(0xffffffffu, sup);
            if (lane == 0) g_mask[b][i][w] = word;
        }
        if (lane < w0) g_mask[b][i][lane] = 0u;
    }
}

// ---------------- kernel 4: exact greedy NMS, skip-ahead warp scan -------------
#define K4_SMEM (TOPK * 32 * 4 + 128)
__global__ void __launch_bounds__(1024, 1)
k4_nms(float* __restrict__ out) {
    extern __shared__ unsigned char smemraw[];
    unsigned int* mask_s = (unsigned int*)smemraw;          // [1000][32]
    unsigned int* keepw  = mask_s + TOPK * 32;              // [32]
    const int b    = blockIdx.x;
    const int tid  = threadIdx.x;
    const int lane = tid & 31;

    // load 128KB mask into smem, vectorized
    {
        const uint4* src = (const uint4*)&g_mask[b][0][0];
        uint4* dst = (uint4*)mask_s;
        #pragma unroll
        for (int v = tid; v < TOPK * 8; v += 1024) dst[v] = src[v];
    }
    __syncthreads();

    if (tid < 32) {
        unsigned int keep = (lane < 31) ? 0xffffffffu : 0xffu;   // 1000 bits
        unsigned int rem  = keep;
        while (true) {
            unsigned int act = __ballot_sync(0xffffffffu, rem != 0u);
            if (!act) break;
            int src = __ffs(act) - 1;
            unsigned int w = __shfl_sync(0xffffffffu, rem, src);
            int bit = __ffs(w) - 1;
            int i = src * 32 + bit;
            if (lane == src) rem &= ~(1u << bit);
            unsigned int row = mask_s[i * 32 + lane];   // bits j<=i are zero
            keep &= ~row;
            rem  &= ~row;
        }
        keepw[lane] = keep;
    }
    __syncthreads();

    if (tid < TOPK) {
        unsigned int kb = (keepw[tid >> 5] >> (tid & 31)) & 1u;
        float s = g_ssc[b][tid];
        bool keep = kb && (s >= 0.05f);
        out[b * TOPK + tid]          = keep ? s : 0.0f;
        out[192000 + b * TOPK + tid] = keep ? 1.0f : 0.0f;
    }
}

// ---------------- launch ------------------------------------------------------
extern "C" void kernel_launch(void* const* d_in, const int* in_sizes, int n_in,
                              void* d_out, int out_size) {
    const float* conf = (const float*)d_in[0];
    const float* cls  = (const float*)d_in[1];
    const float* reg  = (const float*)d_in[2];
    const float* anc  = (const float*)d_in[3];
    float* out = (float*)d_out;

    cudaFuncSetAttribute(k2_select,
                         cudaFuncAttributeMaxDynamicSharedMemorySize, SMEM_BYTES);
    cudaFuncSetAttribute(k4_nms,
                         cudaFuncAttributeMaxDynamicSharedMemorySize, K4_SMEM);

    k1_score<<<(BATCH * MM) / 8, 256>>>(conf, cls);
    k2_select<<<BATCH, 1024, SMEM_BYTES>>>(reg, anc, out);
    k3_mask<<<BATCH * K3_TILES, 256>>>();
    k4_nms<<<BATCH, 1024, K4_SMEM>>>(out);
}

// round 9
// speedup vs baseline: 1.9825x; 1.9825x over previous
#include <cuda_runtime.h>
#include <math.h>
#include <stdint.h>

#define BATCH 32
#define MM 5120
#define NC 80
#define TOPK 1000

// ---------------- scratch (device globals: no allocation allowed) -------------
__device__ float g_scores[BATCH * MM];
__device__ int   g_labels[BATCH * MM];
__device__ float g_ssc[BATCH][TOPK];
__device__ float g_bx1[BATCH][TOPK];
__device__ float g_by1[BATCH][TOPK];
__device__ float g_bx2[BATCH][TOPK];
__device__ float g_by2[BATCH][TOPK];
__device__ float g_bar[BATCH][TOPK];
__device__ __align__(16) unsigned int g_mask[BATCH][TOPK][32];   // 4.1 MB

// ---------------- kernel 1: per-anchor score + label -------------------------
// NUMERICALLY FROZEN (R1-passing version): scores feed a discrete top-k
// selection; any bit change reorders near-ties and corrupts labels output.
__global__ void k1_score(const float* __restrict__ conf,
                         const float* __restrict__ cls) {
    int gw   = (blockIdx.x * blockDim.x + threadIdx.x) >> 5;   // global row
    int lane = threadIdx.x & 31;
    if (gw >= BATCH * MM) return;
    const float* c = cls + (size_t)gw * NC;
    float e0 = c[lane];
    float e1 = c[lane + 32];
    float e2 = (lane < 16) ? c[lane + 64] : -INFINITY;

    float m = e0; int mi = lane;
    if (e1 > m) { m = e1; mi = lane + 32; }
    if (e2 > m) { m = e2; mi = lane + 64; }
    #pragma unroll
    for (int off = 16; off; off >>= 1) {
        float om = __shfl_xor_sync(0xffffffffu, m,  off);
        int   oi = __shfl_xor_sync(0xffffffffu, mi, off);
        if (om > m || (om == m && oi < mi)) { m = om; mi = oi; }
    }
    float s = expf(e0 - m) + expf(e1 - m) + ((lane < 16) ? expf(e2 - m) : 0.0f);
    #pragma unroll
    for (int off = 16; off; off >>= 1)
        s += __shfl_xor_sync(0xffffffffu, s, off);

    if (lane == 0) {
        float cf  = conf[gw];
        float sig = 1.0f / (1.0f + expf(-cf));
        g_scores[gw] = sig / s;
        g_labels[gw] = mi;
    }
}

// ---------------- kernel 2: per-batch exact top-1000 + decode ------------------
#define OFF_HIST   0          // u32[32768]  (128KB)
#define OFF_DKEYS  131072     // u32[5120]
#define OFF_GD     151552     // u32[5120]
#define OFF_GIDX   172032     // u16[5120]
#define OFF_WS     182272     // u32[32]
#define SMEM_BYTES 182784
#define OFF_SIDX   131072     // u32[1000]
#define OFF_SSC    135072     // f32[1000]

__global__ void __launch_bounds__(1024, 1)
k2_select(const float* __restrict__ reg_pred,
          const float* __restrict__ anchors,
          float* __restrict__ out) {
    extern __shared__ unsigned char smem[];
    unsigned int*   hist   = (unsigned int*)(smem + OFF_HIST);
    unsigned int*   dkeys  = (unsigned int*)(smem + OFF_DKEYS);
    unsigned int*   gd     = (unsigned int*)(smem + OFF_GD);
    unsigned short* gidx   = (unsigned short*)(smem + OFF_GIDX);
    unsigned int*   wsums  = (unsigned int*)(smem + OFF_WS);
    unsigned int*   sidx   = (unsigned int*)(smem + OFF_SIDX);
    float*          sscore = (float*)(smem + OFF_SSC);

    const int b    = blockIdx.x;
    const int tid  = threadIdx.x;
    const int warp = tid >> 5;
    const int lane = tid & 31;
    const float* sc = g_scores + (size_t)b * MM;

    for (int i = tid; i < 32768; i += 1024) hist[i] = 0u;
    __syncthreads();

    for (int i = tid; i < MM; i += 1024) {
        unsigned int d = ~__float_as_uint(sc[i]);
        dkeys[i] = d;
        atomicAdd(&hist[d >> 17], 1u);
    }
    __syncthreads();

    {
        int base = tid * 32;
        unsigned int s = 0;
        #pragma unroll 8
        for (int k = 0; k < 32; k++) s += hist[base + k];
        unsigned int v = s;
        #pragma unroll
        for (int off = 1; off < 32; off <<= 1) {
            unsigned int t = __shfl_up_sync(0xffffffffu, v, off);
            if (lane >= off) v += t;
        }
        if (lane == 31) wsums[warp] = v;
        __syncthreads();
        if (tid < 32) {
            unsigned int w = wsums[tid];
            #pragma unroll
            for (int off = 1; off < 32; off <<= 1) {
                unsigned int t = __shfl_up_sync(0xffffffffu, w, off);
                if (tid >= off) w += t;
            }
            wsums[tid] = w;
        }
        __syncthreads();
        unsigned int run = (v - s) + ((warp > 0) ? wsums[warp - 1] : 0u);
        #pragma unroll 8
        for (int k = 0; k < 32; k++) {
            unsigned int h = hist[base + k];
            hist[base + k] = run;
            run += h;
        }
    }
    __syncthreads();

    for (int i = tid; i < MM; i += 1024) {
        unsigned int d = dkeys[i];
        unsigned int p = atomicAdd(&hist[d >> 17], 1u);
        gd[p]   = d;
        gidx[p] = (unsigned short)i;
    }
    __syncthreads();

    for (int p = tid; p < MM; p += 1024) {
        unsigned int d   = gd[p];
        unsigned int idx = gidx[p];
        unsigned int bin = d >> 17;
        unsigned int start = hist[bin - 1];
        if (start >= TOPK) continue;
        unsigned int end = hist[bin];
        unsigned int r = start;
        for (unsigned int q = start; q < end; q++) {
            unsigned int dq = gd[q];
            if (dq < d || (dq == d && gidx[q] < idx)) r++;
        }
        if (r < TOPK) { sidx[r] = idx; sscore[r] = __uint_as_float(~d); }
    }
    __syncthreads();

    for (int k = tid; k < TOPK; k += 1024) {
        unsigned int idx = sidx[k];
        const float* rp = reg_pred + ((size_t)b * MM + idx) * 4;
        float tx = rp[0], ty = rp[1], tw = rp[2], th = rp[3];
        const float* an = anchors + (size_t)idx * 4;
        float ax = an[0], ay = an[1], aw = an[2], ah = an[3];
        float cx = (1.0f / (1.0f + expf(-tx))) * 16.0f + ax;
        float cy = (1.0f / (1.0f + expf(-ty))) * 16.0f + ay;
        float w  = expf(tw) * aw;
        float h  = expf(th) * ah;
        float x1 = fminf(fmaxf((cx - 0.5f * w) * (1.0f / 512.0f), 0.0f), 1.0f);
        float y1 = fminf(fmaxf((cy - 0.5f * h) * (1.0f / 512.0f), 0.0f), 1.0f);
        float x2 = fminf(fmaxf((cx + 0.5f * w) * (1.0f / 512.0f), 0.0f), 1.0f);
        float y2 = fminf(fmaxf((cy + 0.5f * h) * (1.0f / 512.0f), 0.0f), 1.0f);
        float lf  = (float)g_labels[(size_t)b * MM + idx];
        float off = 2.0f * lf;
        float ox1 = x1 + off, oy1 = y1 + off, ox2 = x2 + off, oy2 = y2 + off;
        g_bx1[b][k] = ox1; g_by1[b][k] = oy1;
        g_bx2[b][k] = ox2; g_by2[b][k] = oy2;
        g_bar[b][k] = (ox2 - ox1) * (oy2 - oy1);
        g_ssc[b][k] = sscore[k];
        out[32000 + b * TOPK + k] = lf;
        size_t bb = 64000 + ((size_t)b * TOPK + k) * 4;
        out[bb + 0] = x1; out[bb + 1] = y1; out[bb + 2] = x2; out[bb + 3] = y2;
    }
}

// ---------------- kernel 3: suppression mask, full-chip, load-balanced ---------
// row layout: g_mask[b][i][w] bit (j&31) set iff (j>i) && iou(i,j)>0.6, j=w*32+lane
// strided row assignment: CTA (b,tile), warp w -> rows i = tile + 8*w + 64*r
__global__ void __launch_bounds__(256)
k3_mask() {
    __shared__ float sx1[TOPK], sy1[TOPK], sx2[TOPK], sy2[TOPK], sar[TOPK];
    const int b    = blockIdx.x >> 3;
    const int tile = blockIdx.x & 7;
    const int tid  = threadIdx.x;
    const int warp = tid >> 5;
    const int lane = tid & 31;

    for (int t = tid; t < TOPK; t += 256) {
        sx1[t] = g_bx1[b][t]; sy1[t] = g_by1[b][t];
        sx2[t] = g_bx2[b][t]; sy2[t] = g_by2[b][t];
        sar[t] = g_bar[b][t];
    }
    __syncthreads();

    for (int i = tile + 8 * warp; i < TOPK; i += 64) {
        float ix1 = sx1[i], iy1 = sy1[i], ix2 = sx2[i], iy2 = sy2[i], ia = sar[i];
        int w0 = i >> 5;                 // words below w0 are all-zero (j<i only)
        for (int w = w0; w < 32; w++) {
            int j = w * 32 + lane;
            bool sup = false;
            if (j > i && j < TOPK) {
                float xx1 = fmaxf(sx1[j], ix1);
                float yy1 = fmaxf(sy1[j], iy1);
                float xx2 = fminf(sx2[j], ix2);
                float yy2 = fminf(sy2[j], iy2);
                float ww = fmaxf(1e-28f, xx2 - xx1);
                float hh = fmaxf(1e-28f, yy2 - yy1);
                float inter = ww * hh;
                float iou = inter / (sar[j] + ia - inter + 1e-14f);
                sup = iou > 0.6f;
            }
            unsigned int word = __ballot_sync(0xffffffffu, sup);
            if (lane == 0) g_mask[b][i][w] = word;
        }
        if (lane < w0) g_mask[b][i][lane] = 0u;
    }
}

// ---------------- kernel 4: exact greedy NMS, sparse suppressor-row scan -------
// Serial cost scales with #rows that suppress anything (sparse => tiny),
// not with #kept boxes (the R3 mistake).
#define K4_MASK_WORDS (TOPK * 32)
#define K4_SMEM (K4_MASK_WORDS * 4 + 1024 + 128)
__global__ void __launch_bounds__(1024, 1)
k4_nms(float* __restrict__ out) {
    extern __shared__ unsigned char smemraw[];
    unsigned int*  mask_s  = (unsigned int*)smemraw;               // [1000][32]
    unsigned char* rowany8 = (unsigned char*)(mask_s + K4_MASK_WORDS); // [1000]+pad
    unsigned int*  keepw   = (unsigned int*)(rowany8 + 1024);      // [32]
    const int b    = blockIdx.x;
    const int tid  = threadIdx.x;
    const int lane = tid & 31;
    const int warp = tid >> 5;

    if (tid < TOPK) rowany8[tid] = 0;
    __syncthreads();

    // stage 128KB mask; flag rows with any suppression bit (benign same-value race)
    {
        const uint4* src = (const uint4*)&g_mask[b][0][0];
        uint4* dst = (uint4*)mask_s;
        #pragma unroll
        for (int v = tid; v < TOPK * 8; v += 1024) {
            uint4 val = src[v];
            dst[v] = val;
            if (val.x | val.y | val.z | val.w) rowany8[v >> 3] = 1;
        }
    }
    __syncthreads();

    if (warp == 0) {
        // pack rnz bitmap: lane l owns word l (rows l*32 .. l*32+31)
        unsigned int rnz = 0;
        #pragma unroll 8
        for (int bbit = 0; bbit < 32; bbit++) {
            int r = lane * 32 + bbit;
            if (r < TOPK && rowany8[r]) rnz |= 1u << bbit;
        }
        unsigned int sup = 0;      // accumulated suppressed bits for word `lane`
        unsigned int mykeep = 0;
        #pragma unroll 1
        for (int t = 0; t < 32; t++) {
            unsigned int init = (t < 31) ? 0xffffffffu : 0xffu;  // 1000 bits
            unsigned int kw  = init & ~__shfl_sync(0xffffffffu, sup, t);
            unsigned int act = kw & __shfl_sync(0xffffffffu, rnz, t);
            while (act) {
                int bb = __ffs(act) - 1;
                int i  = t * 32 + bb;
                unsigned int row = mask_s[i * 32 + lane];   // bits j<=i are zero
                unsigned int rw  = __shfl_sync(0xffffffffu, row, t);
                kw  &= ~rw;
                act &= ~rw;
                act &= ~(1u << bb);
                sup |= row;
            }
            if (lane == t) mykeep = kw;
        }
        keepw[lane] = mykeep;
    }
    __syncthreads();

    if (tid < TOPK) {
        unsigned int kb = (keepw[tid >> 5] >> (tid & 31)) & 1u;
        float s = g_ssc[b][tid];
        bool keep = kb && (s >= 0.05f);
        out[b * TOPK + tid]          = keep ? s : 0.0f;
        out[192000 + b * TOPK + tid] = keep ? 1.0f : 0.0f;
    }
}

// ---------------- launch ------------------------------------------------------
extern "C" void kernel_launch(void* const* d_in, const int* in_sizes, int n_in,
                              void* d_out, int out_size) {
    const float* conf = (const float*)d_in[0];
    const float* cls  = (const float*)d_in[1];
    const float* reg  = (const float*)d_in[2];
    const float* anc  = (const float*)d_in[3];
    float* out = (float*)d_out;

    cudaFuncSetAttribute(k2_select,
                         cudaFuncAttributeMaxDynamicSharedMemorySize, SMEM_BYTES);
    cudaFuncSetAttribute(k4_nms,
                         cudaFuncAttributeMaxDynamicSharedMemorySize, K4_SMEM);

    k1_score<<<(BATCH * MM) / 8, 256>>>(conf, cls);
    k2_select<<<BATCH, 1024, SMEM_BYTES>>>(reg, anc, out);
    k3_mask<<<BATCH * 8, 256>>>();
    k4_nms<<<BATCH, 1024, K4_SMEM>>>(out);
}

// round 11
// speedup vs baseline: 2.1071x; 1.0629x over previous
#include <cuda_runtime.h>
#include <math.h>
#include <stdint.h>

#define BATCH 32
#define MM 5120
#define NC 80
#define TOPK 1000

// ---------------- scratch (device globals: no allocation allowed) -------------
__device__ float g_scores[BATCH * MM];
__device__ int   g_labels[BATCH * MM];
__device__ float g_ssc[BATCH][TOPK];
__device__ float g_bx1[BATCH][TOPK];
__device__ float g_by1[BATCH][TOPK];
__device__ float g_bx2[BATCH][TOPK];
__device__ float g_by2[BATCH][TOPK];
__device__ float g_bar[BATCH][TOPK];
__device__ __align__(16) unsigned int g_mask[BATCH][TOPK][32];   // 4.1 MB
__device__ unsigned char g_rowany[BATCH][TOPK];

// ---------------- kernel 1: per-anchor score + label -------------------------
// NUMERICALLY FROZEN (R1-passing version): scores feed a discrete top-k
// selection; any bit change reorders near-ties and corrupts labels output.
__global__ void k1_score(const float* __restrict__ conf,
                         const float* __restrict__ cls) {
    int gw   = (blockIdx.x * blockDim.x + threadIdx.x) >> 5;   // global row
    int lane = threadIdx.x & 31;
    if (gw >= BATCH * MM) return;
    const float* c = cls + (size_t)gw * NC;
    float e0 = c[lane];
    float e1 = c[lane + 32];
    float e2 = (lane < 16) ? c[lane + 64] : -INFINITY;

    float m = e0; int mi = lane;
    if (e1 > m) { m = e1; mi = lane + 32; }
    if (e2 > m) { m = e2; mi = lane + 64; }
    #pragma unroll
    for (int off = 16; off; off >>= 1) {
        float om = __shfl_xor_sync(0xffffffffu, m,  off);
        int   oi = __shfl_xor_sync(0xffffffffu, mi, off);
        if (om > m || (om == m && oi < mi)) { m = om; mi = oi; }
    }
    float s = expf(e0 - m) + expf(e1 - m) + ((lane < 16) ? expf(e2 - m) : 0.0f);
    #pragma unroll
    for (int off = 16; off; off >>= 1)
        s += __shfl_xor_sync(0xffffffffu, s, off);

    if (lane == 0) {
        float cf  = conf[gw];
        float sig = 1.0f / (1.0f + expf(-cf));
        g_scores[gw] = sig / s;
        g_labels[gw] = mi;
    }
}

// ---------------- kernel 2: per-batch exact top-1000 + decode ------------------
#define OFF_HIST   0          // u32[32768]  (128KB)
#define OFF_DKEYS  131072     // u32[5120]
#define OFF_GD     151552     // u32[5120]
#define OFF_GIDX   172032     // u16[5120]
#define OFF_WS     182272     // u32[32]
#define SMEM_BYTES 182784
#define OFF_SIDX   131072     // u32[1000]
#define OFF_SSC    135072     // f32[1000]

__global__ void __launch_bounds__(1024, 1)
k2_select(const float* __restrict__ reg_pred,
          const float* __restrict__ anchors,
          float* __restrict__ out) {
    extern __shared__ unsigned char smem[];
    unsigned int*   hist   = (unsigned int*)(smem + OFF_HIST);
    unsigned int*   dkeys  = (unsigned int*)(smem + OFF_DKEYS);
    unsigned int*   gd     = (unsigned int*)(smem + OFF_GD);
    unsigned short* gidx   = (unsigned short*)(smem + OFF_GIDX);
    unsigned int*   wsums  = (unsigned int*)(smem + OFF_WS);
    unsigned int*   sidx   = (unsigned int*)(smem + OFF_SIDX);
    float*          sscore = (float*)(smem + OFF_SSC);

    const int b    = blockIdx.x;
    const int tid  = threadIdx.x;
    const int warp = tid >> 5;
    const int lane = tid & 31;
    const float* sc = g_scores + (size_t)b * MM;

    // ---- S1: zero histogram (lane-contiguous: conflict-free) ----
    for (int i = tid; i < 32768; i += 1024) hist[i] = 0u;
    __syncthreads();

    // ---- S2: keys + histogram. key d = ~bits(score): ascending d == descending score.
    for (int i = tid; i < MM; i += 1024) {
        unsigned int d = ~__float_as_uint(sc[i]);
        dkeys[i] = d;
        atomicAdd(&hist[d >> 17], 1u);
    }
    __syncthreads();

    // ---- S3: exclusive prefix sum over 32768 bins, CONFLICT-FREE.
    // warp w owns bins [w*1024, w*1024+1024): 32 lane-contiguous rows of 32,
    // warp-serial running scan; then scan the 32 warp totals; then add-back.
    {
        const int wb = warp * 1024;
        unsigned int run = 0;
        for (int k = 0; k < 32; k++) {
            int idx = wb + k * 32 + lane;
            unsigned int v = hist[idx];
            unsigned int inc = v;
            #pragma unroll
            for (int off = 1; off < 32; off <<= 1) {
                unsigned int t = __shfl_up_sync(0xffffffffu, inc, off);
                if (lane >= off) inc += t;
            }
            hist[idx] = run + inc - v;      // exclusive within warp's block
            run += __shfl_sync(0xffffffffu, inc, 31);
        }
        if (lane == 0) wsums[warp] = run;
        __syncthreads();
        if (tid < 32) {
            unsigned int w = wsums[tid];
            unsigned int incl = w;
            #pragma unroll
            for (int off = 1; off < 32; off <<= 1) {
                unsigned int t = __shfl_up_sync(0xffffffffu, incl, off);
                if (tid >= off) incl += t;
            }
            wsums[tid] = incl - w;          // exclusive warp offset
        }
        __syncthreads();
        unsigned int off0 = wsums[warp];
        if (off0) {
            for (int k = 0; k < 32; k++)
                hist[wb + k * 32 + lane] += off0;
        }
    }
    __syncthreads();

    // ---- S4: scatter into bin-grouped order (post: hist[b] = cum[b+1]) ----
    for (int i = tid; i < MM; i += 1024) {
        unsigned int d = dkeys[i];
        unsigned int p = atomicAdd(&hist[d >> 17], 1u);
        gd[p]   = d;
        gidx[p] = (unsigned short)i;
    }
    __syncthreads();

    // ---- S5: exact rank within bin -> top-1000 (stable: (score desc, idx asc)) ----
    for (int p = tid; p < MM; p += 1024) {
        unsigned int d   = gd[p];
        unsigned int idx = gidx[p];
        unsigned int bin = d >> 17;
        unsigned int start = hist[bin - 1];   // == cum[bin] after S4
        if (start >= TOPK) continue;
        unsigned int end = hist[bin];         // == cum[bin+1]
        unsigned int r = start;
        for (unsigned int q = start; q < end; q++) {
            unsigned int dq = gd[q];
            if (dq < d || (dq == d && gidx[q] < idx)) r++;
        }
        if (r < TOPK) { sidx[r] = idx; sscore[r] = __uint_as_float(~d); }
    }
    __syncthreads();

    // ---- S6: decode boxes; outputs labels/bboxes; stash offset boxes to globals --
    for (int k = tid; k < TOPK; k += 1024) {
        unsigned int idx = sidx[k];
        const float* rp = reg_pred + ((size_t)b * MM + idx) * 4;
        float tx = rp[0], ty = rp[1], tw = rp[2], th = rp[3];
        const float* an = anchors + (size_t)idx * 4;
        float ax = an[0], ay = an[1], aw = an[2], ah = an[3];
        float cx = (1.0f / (1.0f + expf(-tx))) * 16.0f + ax;
        float cy = (1.0f / (1.0f + expf(-ty))) * 16.0f + ay;
        float w  = expf(tw) * aw;
        float h  = expf(th) * ah;
        float x1 = fminf(fmaxf((cx - 0.5f * w) * (1.0f / 512.0f), 0.0f), 1.0f);
        float y1 = fminf(fmaxf((cy - 0.5f * h) * (1.0f / 512.0f), 0.0f), 1.0f);
        float x2 = fminf(fmaxf((cx + 0.5f * w) * (1.0f / 512.0f), 0.0f), 1.0f);
        float y2 = fminf(fmaxf((cy + 0.5f * h) * (1.0f / 512.0f), 0.0f), 1.0f);
        float lf  = (float)g_labels[(size_t)b * MM + idx];
        float off = 2.0f * lf;
        float ox1 = x1 + off, oy1 = y1 + off, ox2 = x2 + off, oy2 = y2 + off;
        g_bx1[b][k] = ox1; g_by1[b][k] = oy1;
        g_bx2[b][k] = ox2; g_by2[b][k] = oy2;
        g_bar[b][k] = (ox2 - ox1) * (oy2 - oy1);
        g_ssc[b][k] = sscore[k];
        out[32000 + b * TOPK + k] = lf;
        size_t bb = 64000 + ((size_t)b * TOPK + k) * 4;
        out[bb + 0] = x1; out[bb + 1] = y1; out[bb + 2] = x2; out[bb + 3] = y2;
    }
}

// ---------------- kernel 3: suppression mask + row flags, full-chip ------------
// row layout: g_mask[b][i][w] bit (j&31) set iff (j>i) && iou(i,j)>0.6, j=w*32+lane
// strided row assignment: CTA (b,tile), warp w -> rows i = tile + 8*w + 64*r
__global__ void __launch_bounds__(256)
k3_mask() {
    __shared__ float sx1[TOPK], sy1[TOPK], sx2[TOPK], sy2[TOPK], sar[TOPK];
    const int b    = blockIdx.x >> 3;
    const int tile = blockIdx.x & 7;
    const int tid  = threadIdx.x;
    const int warp = tid >> 5;
    const int lane = tid & 31;

    for (int t = tid; t < TOPK; t += 256) {
        sx1[t] = g_bx1[b][t]; sy1[t] = g_by1[b][t];
        sx2[t] = g_bx2[b][t]; sy2[t] = g_by2[b][t];
        sar[t] = g_bar[b][t];
    }
    __syncthreads();

    for (int i = tile + 8 * warp; i < TOPK; i += 64) {
        float ix1 = sx1[i], iy1 = sy1[i], ix2 = sx2[i], iy2 = sy2[i], ia = sar[i];
        int w0 = i >> 5;                 // words below w0 are all-zero (j<i only)
        unsigned int any = 0;
        for (int w = w0; w < 32; w++) {
            int j = w * 32 + lane;
            bool sup = false;
            if (j > i && j < TOPK) {
                float xx1 = fmaxf(sx1[j], ix1);
                float yy1 = fmaxf(sy1[j], iy1);
                float xx2 = fminf(sx2[j], ix2);
                float yy2 = fminf(sy2[j], iy2);
                float ww = fmaxf(1e-28f, xx2 - xx1);
                float hh = fmaxf(1e-28f, yy2 - yy1);
                float inter = ww * hh;
                float iou = inter / (sar[j] + ia - inter + 1e-14f);
                sup = iou > 0.6f;
            }
            unsigned int word = __ballot_sync(0xffffffffu, sup);
            if (lane == 0) { g_mask[b][i][w] = word; any |= word; }
        }
        if (lane < w0) g_mask[b][i][lane] = 0u;
        if (lane == 0) g_rowany[b][i] = any ? 1 : 0;
    }
}

// ---------------- kernel 4: exact greedy NMS, compact sparse rows --------------
// Only rows flagged by k3 are staged (coalesced 128B each); serial scan visits
// only kept flagged rows. No 128KB bulk copy (the R9 k4 bottleneck).
#define K4_MAXS 512
#define OFF4_MASK  0                               // u32[K4_MAXS][32] = 64KB
#define OFF4_FL    (K4_MAXS * 32 * 4)              // u8[1024]
#define OFF4_RNZ   (OFF4_FL + 1024)                // u32[32]
#define OFF4_WB    (OFF4_RNZ + 128)                // u32[32]
#define OFF4_KEEP  (OFF4_WB + 128)                 // u32[32]
#define K4_SMEM    (OFF4_KEEP + 128)
__global__ void __launch_bounds__(1024, 1)
k4_nms(float* __restrict__ out) {
    extern __shared__ unsigned char smemraw[];
    unsigned int*  mask_s = (unsigned int*)(smemraw + OFF4_MASK);
    unsigned char* fl8    = (unsigned char*)(smemraw + OFF4_FL);
    unsigned int*  rnz_s  = (unsigned int*)(smemraw + OFF4_RNZ);
    unsigned int*  wb_s   = (unsigned int*)(smemraw + OFF4_WB);
    unsigned int*  keepw  = (unsigned int*)(smemraw + OFF4_KEEP);
    const int b    = blockIdx.x;
    const int tid  = threadIdx.x;
    const int lane = tid & 31;
    const int warp = tid >> 5;

    // load row flags (pad to 1024)
    fl8[tid] = (tid < TOPK) ? g_rowany[b][tid] : 0;
    __syncthreads();

    // pack rnz bitmap: warp w owns word w
    {
        unsigned int word = __ballot_sync(0xffffffffu, fl8[warp * 32 + lane] != 0);
        if (lane == 0) rnz_s[warp] = word;
    }
    __syncthreads();

    // exclusive prefix popcount -> compact slot bases
    if (tid < 32) {
        unsigned int v = __popc(rnz_s[tid]);
        unsigned int incl = v;
        #pragma unroll
        for (int off = 1; off < 32; off <<= 1) {
            unsigned int t = __shfl_up_sync(0xffffffffu, incl, off);
            if (tid >= off) incl += t;
        }
        wb_s[tid] = incl - v;
    }
    __syncthreads();

    // stage flagged rows into compact slots (coalesced 128B per row)
    for (int r = warp; r < TOPK; r += 32) {
        if (fl8[r]) {
            unsigned int s = wb_s[r >> 5] +
                             __popc(rnz_s[r >> 5] & ((1u << (r & 31)) - 1u));
            if (s < K4_MAXS)
                mask_s[s * 32 + lane] = g_mask[b][r][lane];
        }
    }
    __syncthreads();

    if (warp == 0) {
        unsigned int rnzl = rnz_s[lane];
        unsigned int wbl  = wb_s[lane];
        unsigned int sup = 0;      // accumulated suppressed bits for word `lane`
        unsigned int mykeep = 0;
        #pragma unroll 1
        for (int t = 0; t < 32; t++) {
            unsigned int init = (t < 31) ? 0xffffffffu : 0xffu;  // 1000 bits
            unsigned int kw  = init & ~__shfl_sync(0xffffffffu, sup, t);
            unsigned int rt  = __shfl_sync(0xffffffffu, rnzl, t);
            unsigned int wbt = __shfl_sync(0xffffffffu, wbl, t);
            unsigned int act = kw & rt;
            while (act) {
                int bb = __ffs(act) - 1;
                int i  = t * 32 + bb;
                unsigned int s = wbt + __popc(rt & ((1u << bb) - 1u));
                unsigned int row = (s < K4_MAXS) ? mask_s[s * 32 + lane]
                                                 : g_mask[b][i][lane];
                unsigned int rw  = __shfl_sync(0xffffffffu, row, t);
                kw  &= ~rw;
                act &= ~rw;
                act &= ~(1u << bb);
                sup |= row;
            }
            if (lane == t) mykeep = kw;
        }
        keepw[lane] = mykeep;
    }
    __syncthreads();

    if (tid < TOPK) {
        unsigned int kb = (keepw[tid >> 5] >> (tid & 31)) & 1u;
        float s = g_ssc[b][tid];
        bool keep = kb && (s >= 0.05f);
        out[b * TOPK + tid]          = keep ? s : 0.0f;
        out[192000 + b * TOPK + tid] = keep ? 1.0f : 0.0f;
    }
}

// ---------------- launch ------------------------------------------------------
extern "C" void kernel_launch(void* const* d_in, const int* in_sizes, int n_in,
                              void* d_out, int out_size) {
    const float* conf = (const float*)d_in[0];
    const float* cls  = (const float*)d_in[1];
    const float* reg  = (const float*)d_in[2];
    const float* anc  = (const float*)d_in[3];
    float* out = (float*)d_out;

    cudaFuncSetAttribute(k2_select,
                         cudaFuncAttributeMaxDynamicSharedMemorySize, SMEM_BYTES);
    cudaFuncSetAttribute(k4_nms,
                         cudaFuncAttributeMaxDynamicSharedMemorySize, K4_SMEM);

    k1_score<<<(BATCH * MM) / 8, 256>>>(conf, cls);
    k2_select<<<BATCH, 1024, SMEM_BYTES>>>(reg, anc, out);
    k3_mask<<<BATCH * 8, 256>>>();
    k4_nms<<<BATCH, 1024, K4_SMEM>>>(out);
}